// round 16
// baseline (speedup 1.0000x reference)
#include <cuda_runtime.h>
#include <cuda_bf16.h>
#include <mma.h>
#include <cstdint>

using namespace nvcuda;

// Problem constants
#define B_  2
#define S_  2048
#define E_  1024
#define NH_ 16
#define NKV_ 4
#define HD_ 64
#define GS_ 4
#define MTOT (B_*S_)    // 4096

// ---------------- scratch ----------------
__device__ __align__(16) float g_attn[MTOT * 1024];
__device__ __align__(16) __nv_bfloat16 g_qah[MTOT*1024], g_qal[MTOT*1024];           // Q scaled, [b][s][h*64+d]
__device__ __align__(16) __nv_bfloat16 g_kah[B_*NKV_*S_*HD_], g_kal[B_*NKV_*S_*HD_]; // [b][kvh][s][d]
__device__ __align__(16) __nv_bfloat16 g_vth[B_*NKV_*S_*HD_], g_vtl[B_*NKV_*S_*HD_]; // [b][kvh][d][s]

// ---------------- helpers ----------------
__device__ __forceinline__ uint32_t pack2(float x, float y) {
    __nv_bfloat162 t = __floats2bfloat162_rn(x, y);
    return *(uint32_t*)&t;
}
__device__ __forceinline__ float bf16hi(float x) {
    return __bfloat162float(__float2bfloat16_rn(x));
}
__device__ __forceinline__ void split2(float2 v, uint32_t& hi, uint32_t& lo) {
    float hx = bf16hi(v.x), hy = bf16hi(v.y);
    hi = pack2(hx, hy);
    lo = pack2(v.x - hx, v.y - hy);
}
__device__ __forceinline__ void mma_bf16(float c[4], const uint32_t a[4],
                                         uint32_t b0, uint32_t b1)
{
    asm volatile(
        "mma.sync.aligned.m16n8k16.row.col.f32.bf16.bf16.f32 "
        "{%0,%1,%2,%3}, {%4,%5,%6,%7}, {%8,%9}, {%0,%1,%2,%3};"
        : "+f"(c[0]), "+f"(c[1]), "+f"(c[2]), "+f"(c[3])
        : "r"(a[0]), "r"(a[1]), "r"(a[2]), "r"(a[3]), "r"(b0), "r"(b1));
}
__device__ __forceinline__ void cp16(void* smem_dst, const void* gsrc) {
    uint32_t d = (uint32_t)__cvta_generic_to_shared(smem_dst);
    asm volatile("cp.async.cg.shared.global [%0], [%1], 16;" :: "r"(d), "l"(gsrc));
}
__device__ __forceinline__ void ldm4(uint32_t r[4], uint32_t addr) {
    asm volatile("ldmatrix.sync.aligned.m8n8.x4.shared.b16 {%0,%1,%2,%3}, [%4];"
        : "=r"(r[0]), "=r"(r[1]), "=r"(r[2]), "=r"(r[3]) : "r"(addr));
}

// ---------------------------------------------------------------------------
// tf32 GEMM mainloop (3-stage cp.async, cvt-in-fragment).
// Block 128x128, BK=16, 8 warps, warp 64x32.
// ---------------------------------------------------------------------------
#define GBK 16
#define GPAD 20
#define GSTAGE_F (128 * GPAD)
#define EPST 132    // epilogue staging stride: multiple of 4 floats (wmma ldm req.)

typedef wmma::fragment<wmma::accumulator, 16, 16, 8, float> AccFrag;

__device__ __forceinline__ void gemm_mainloop(const float* __restrict__ X,
                                              const float* __restrict__ W,
                                              int K, float* sm,
                                              AccFrag acc[4][2], int m0, int n0)
{
    float* Xs = sm;
    float* Ws = sm + 3 * GSTAGE_F;

    const int tid = threadIdx.x;
    const int wid = tid >> 5;
    const int wr  = wid & 1;
    const int wc  = wid >> 1;

    #pragma unroll
    for (int i = 0; i < 4; i++)
        #pragma unroll
        for (int j = 0; j < 2; j++)
            wmma::fill_fragment(acc[i][j], 0.0f);

    auto prefetch = [&](int kt, int st) {
        const int k0 = kt * GBK;
        float* xs = Xs + st * GSTAGE_F;
        float* ws = Ws + st * GSTAGE_F;
        #pragma unroll
        for (int l = 0; l < 2; l++) {
            int idx = tid + l * 256;
            int r   = idx >> 2;
            int c4  = idx & 3;
            cp16(&xs[r * GPAD + c4 * 4], &X[(size_t)(m0 + r) * K + k0 + c4 * 4]);
            cp16(&ws[r * GPAD + c4 * 4], &W[(size_t)(n0 + r) * K + k0 + c4 * 4]);
        }
        asm volatile("cp.async.commit_group;");
    };

    const int nKT = K / GBK;
    prefetch(0, 0);
    if (nKT > 1) prefetch(1, 1);

    int pst = 2;
    for (int kt = 0; kt < nKT; kt++) {
        asm volatile("cp.async.wait_group 1;");
        __syncthreads();
        if (kt + 2 < nKT) {
            prefetch(kt + 2, pst);
            pst = (pst + 1 == 3) ? 0 : pst + 1;
        } else {
            asm volatile("cp.async.commit_group;");
        }
        const int st = kt % 3;
        const float* xs = Xs + st * GSTAGE_F;
        const float* ws = Ws + st * GSTAGE_F;

        #pragma unroll
        for (int ks = 0; ks < GBK; ks += 8) {
            wmma::fragment<wmma::matrix_a, 16, 16, 8, wmma::precision::tf32, wmma::row_major> a[4];
            wmma::fragment<wmma::matrix_b, 16, 16, 8, wmma::precision::tf32, wmma::col_major> bfr[2];
            #pragma unroll
            for (int i = 0; i < 4; i++) {
                wmma::load_matrix_sync(a[i], &xs[(wr * 64 + i * 16) * GPAD + ks], GPAD);
                #pragma unroll
                for (int t = 0; t < a[i].num_elements; t++)
                    a[i].x[t] = wmma::__float_to_tf32(a[i].x[t]);
            }
            #pragma unroll
            for (int j = 0; j < 2; j++) {
                wmma::load_matrix_sync(bfr[j], &ws[(wc * 32 + j * 16) * GPAD + ks], GPAD);
                #pragma unroll
                for (int t = 0; t < bfr[j].num_elements; t++)
                    bfr[j].x[t] = wmma::__float_to_tf32(bfr[j].x[t]);
            }
            #pragma unroll
            for (int i = 0; i < 4; i++)
                #pragma unroll
                for (int j = 0; j < 2; j++)
                    wmma::mma_sync(acc[i][j], a[i], bfr[j], acc[i][j]);
        }
    }
}

// ---------------------------------------------------------------------------
// Batched projection kernel: z=0 Q-proj, z=1 K-proj, z=2 V-proj.
// Epilogue stages C tile in smem, emits bf16 hi/lo in attention layouts.
// ---------------------------------------------------------------------------
__global__ __launch_bounds__(256, 2)
void proj_kernel(const float* __restrict__ Xq, const float* __restrict__ Wq,
                 const float* __restrict__ Xk, const float* __restrict__ Wk,
                 const float* __restrict__ Xv, const float* __restrict__ Wv,
                 uint32_t* __restrict__ qah, uint32_t* __restrict__ qal,
                 uint32_t* __restrict__ kah, uint32_t* __restrict__ kal,
                 uint32_t* __restrict__ vth, uint32_t* __restrict__ vtl)
{
    extern __shared__ float sm[];
    const int z = blockIdx.z;
    if (z > 0 && blockIdx.x >= 2) return;

    const float *X, *W;
    if (z == 0)      { X = Xq; W = Wq; }
    else if (z == 1) { X = Xk; W = Wk; }
    else             { X = Xv; W = Wv; }

    const int m0 = blockIdx.y * 128;
    const int n0 = blockIdx.x * 128;
    const int tid = threadIdx.x;
    const int wid = tid >> 5;
    const int wr  = wid & 1;
    const int wc  = wid >> 1;

    AccFrag acc[4][2];
    gemm_mainloop(X, W, E_, sm, acc, m0, n0);

    // ---- stage C tile to smem [128][EPST] ----
    __syncthreads();
    #pragma unroll
    for (int i = 0; i < 4; i++)
        #pragma unroll
        for (int j = 0; j < 2; j++)
            wmma::store_matrix_sync(&sm[(wr * 64 + i * 16) * EPST + wc * 32 + j * 16],
                                    acc[i][j], EPST, wmma::mem_row_major);
    __syncthreads();

    const int b     = m0 >> 11;
    const int sbase = m0 & 2047;

    if (z == 0) {
        // Q: scale 0.125, split, linear layout [m][1024] as u32 pairs
        for (int i = tid; i < 128 * 64; i += 256) {
            int r = i >> 6, p = i & 63;
            float2 v = *(float2*)&sm[r * EPST + 2 * p];
            v.x *= 0.125f; v.y *= 0.125f;
            uint32_t hi, lo;
            split2(v, hi, lo);
            size_t o = (size_t)(m0 + r) * 512 + (n0 >> 1) + p;
            qah[o] = hi; qal[o] = lo;
        }
    } else if (z == 1) {
        // K: [b][kvh][s][d] as u32 pairs along d
        for (int i = tid; i < 128 * 64; i += 256) {
            int r = i >> 6, p = i & 63;
            float2 v = *(float2*)&sm[r * EPST + 2 * p];
            uint32_t hi, lo;
            split2(v, hi, lo);
            int col = n0 + 2 * p;
            int kvh = col >> 6, d = col & 63;
            size_t o = ((size_t)((b * 4 + kvh) * 2048 + sbase + r)) * 32 + (d >> 1);
            kah[o] = hi; kal[o] = lo;
        }
    } else {
        // V: transposed [b][kvh][d][s] as u32 pairs along s
        for (int i = tid; i < 128 * 64; i += 256) {
            int c = i >> 6, rp = i & 63;
            float a = sm[(2 * rp) * EPST + c];
            float bv = sm[(2 * rp + 1) * EPST + c];
            float ha = bf16hi(a), hb = bf16hi(bv);
            uint32_t hi = pack2(ha, hb);
            uint32_t lo = pack2(a - ha, bv - hb);
            int col = n0 + c;
            int kvh = col >> 6, d = col & 63;
            size_t o = ((size_t)((b * 4 + kvh) * 64 + d)) * 1024 + (sbase >> 1) + rp;
            vth[o] = hi; vtl[o] = lo;
        }
    }
}

// ---------------------------------------------------------------------------
// Plain tf32 GEMM (f32 store) for O projection.
// ---------------------------------------------------------------------------
__global__ __launch_bounds__(256, 2)
void gemm_o_kernel(const float* __restrict__ X, const float* __restrict__ W,
                   float* __restrict__ C, int M, int N, int K)
{
    extern __shared__ float sm[];
    const int m0 = blockIdx.y * 128;
    const int n0 = blockIdx.x * 128;
    const int wid = threadIdx.x >> 5;
    const int wr  = wid & 1;
    const int wc  = wid >> 1;

    AccFrag acc[4][2];
    gemm_mainloop(X, W, K, sm, acc, m0, n0);

    #pragma unroll
    for (int i = 0; i < 4; i++)
        #pragma unroll
        for (int j = 0; j < 2; j++)
            wmma::store_matrix_sync(&C[(size_t)(m0 + wr * 64 + i * 16) * N + n0 + wc * 32 + j * 16],
                                    acc[i][j], N, wmma::mem_row_major);
}

// ---------------------------------------------------------------------------
// Flash attention: BQ=128 (8 warps), BK=32, bf16 hi/lo mma, ldmatrix feeds,
// 2-stage cp.async double buffering.
// ---------------------------------------------------------------------------
#define ABQ 128
#define ABK 32

__global__ __launch_bounds__(256, 2)
void attn_mma_kernel(const uint32_t* __restrict__ qh, const uint32_t* __restrict__ ql,
                     const __nv_bfloat16* __restrict__ kh, const __nv_bfloat16* __restrict__ kl,
                     const __nv_bfloat16* __restrict__ vth, const __nv_bfloat16* __restrict__ vtl,
                     float* __restrict__ O)
{
    __shared__ __align__(16) uint32_t sK[2][2][32 * 36];
    __shared__ __align__(16) uint32_t sV[2][2][64 * 20];

    const int qb   = gridDim.x - 1 - blockIdx.x;
    const int h    = blockIdx.y;
    const int b    = blockIdx.z;
    const int kvh  = h >> 2;
    const int tid  = threadIdx.x;
    const int lane = tid & 31;
    const int w    = tid >> 5;
    const int g    = lane >> 2;
    const int tig  = lane & 3;

    const int r0g = qb * ABQ + w * 16 + g;
    const int r1g = r0g + 8;

    const int sel  = lane >> 3;
    const int rowm = lane & 7;
    const int kofsB = ((((sel >> 1) * 8 + rowm) * 36) + (sel & 1) * 4) * 4;
    const int vofsB = ((((sel >> 1) * 8 + rowm) * 20) + (sel & 1) * 4) * 4;

    uint32_t qhi[4][4], qlo[4][4];
    {
        const size_t b0 = (((size_t)(b * S_ + r0g)) * 1024 + h * 64) >> 1;
        const size_t b1 = (((size_t)(b * S_ + r1g)) * 1024 + h * 64) >> 1;
        #pragma unroll
        for (int kc = 0; kc < 4; kc++) {
            int c0 = kc * 8 + tig, c1 = c0 + 4;
            qhi[kc][0] = qh[b0 + c0]; qhi[kc][1] = qh[b1 + c0];
            qhi[kc][2] = qh[b0 + c1]; qhi[kc][3] = qh[b1 + c1];
            qlo[kc][0] = ql[b0 + c0]; qlo[kc][1] = ql[b1 + c0];
            qlo[kc][2] = ql[b0 + c1]; qlo[kc][3] = ql[b1 + c1];
        }
    }

    float oacc[8][4];
    #pragma unroll
    for (int nb = 0; nb < 8; nb++)
        #pragma unroll
        for (int e = 0; e < 4; e++) oacc[nb][e] = 0.f;
    float m0 = -1e30f, m1 = -1e30f, l0 = 0.f, l1 = 0.f;

    const int wRowMax = qb * ABQ + w * 16 + 15;
    const int nKT = 4 * qb + 4;
    const size_t kbase = ((size_t)(b * NKV_ + kvh)) * S_ * 64;
    const size_t vbase = ((size_t)(b * NKV_ + kvh)) * 64 * S_;

    auto load_tile = [&](int kt, int st) {
        #pragma unroll
        for (int l = 0; l < 4; l++) {
            int idx = tid + l * 256;
            if (idx < 512) {
                int c = idx & 7, r = (idx >> 3) & 31, hl = idx >> 8;
                const __nv_bfloat16* src = (hl ? kl : kh) + kbase + (size_t)(kt * 32 + r) * 64 + c * 8;
                cp16(&sK[st][hl][r * 36 + c * 4], src);
            } else {
                int j = idx - 512;
                int c = j & 3, d = (j >> 2) & 63, hl = j >> 8;
                const __nv_bfloat16* src = (hl ? vtl : vth) + vbase + (size_t)d * S_ + kt * 32 + c * 8;
                cp16(&sV[st][hl][d * 20 + c * 4], src);
            }
        }
        asm volatile("cp.async.commit_group;");
    };

    load_tile(0, 0);

    for (int kt = 0; kt < nKT; kt++) {
        asm volatile("cp.async.wait_group 0;");
        __syncthreads();
        if (kt + 1 < nKT) load_tile(kt + 1, (kt + 1) & 1);
        const int st = kt & 1;

        if (kt * ABK <= wRowMax) {
            const uint32_t aKhi = (uint32_t)__cvta_generic_to_shared(&sK[st][0][0]);
            const uint32_t aKlo = (uint32_t)__cvta_generic_to_shared(&sK[st][1][0]);
            const uint32_t aVhi = (uint32_t)__cvta_generic_to_shared(&sV[st][0][0]);
            const uint32_t aVlo = (uint32_t)__cvta_generic_to_shared(&sV[st][1][0]);

            float sacc[4][4];
            #pragma unroll
            for (int nb = 0; nb < 4; nb++)
                #pragma unroll
                for (int e = 0; e < 4; e++) sacc[nb][e] = 0.f;

            #pragma unroll
            for (int kc = 0; kc < 4; kc++) {
                #pragma unroll
                for (int nbp = 0; nbp < 2; nbp++) {
                    uint32_t off = (uint32_t)((nbp * 16 * 36 + kc * 8) * 4) + kofsB;
                    uint32_t H[4], L[4];
                    ldm4(H, aKhi + off);
                    ldm4(L, aKlo + off);
                    mma_bf16(sacc[2*nbp],   qhi[kc], L[0], L[1]);
                    mma_bf16(sacc[2*nbp],   qlo[kc], H[0], H[1]);
                    mma_bf16(sacc[2*nbp],   qhi[kc], H[0], H[1]);
                    mma_bf16(sacc[2*nbp+1], qhi[kc], L[2], L[3]);
                    mma_bf16(sacc[2*nbp+1], qlo[kc], H[2], H[3]);
                    mma_bf16(sacc[2*nbp+1], qhi[kc], H[2], H[3]);
                }
            }

            float mn0 = m0, mn1 = m1;
            #pragma unroll
            for (int nb = 0; nb < 4; nb++) {
                #pragma unroll
                for (int e = 0; e < 2; e++) {
                    int col = kt * ABK + nb * 8 + 2 * tig + e;
                    if (col > r0g) sacc[nb][e]     = -1e30f;
                    if (col > r1g) sacc[nb][e + 2] = -1e30f;
                    mn0 = fmaxf(mn0, sacc[nb][e]);
                    mn1 = fmaxf(mn1, sacc[nb][e + 2]);
                }
            }
            mn0 = fmaxf(mn0, __shfl_xor_sync(0xffffffffu, mn0, 1));
            mn0 = fmaxf(mn0, __shfl_xor_sync(0xffffffffu, mn0, 2));
            mn1 = fmaxf(mn1, __shfl_xor_sync(0xffffffffu, mn1, 1));
            mn1 = fmaxf(mn1, __shfl_xor_sync(0xffffffffu, mn1, 2));

            const float corr0 = __expf(m0 - mn0);
            const float corr1 = __expf(m1 - mn1);
            m0 = mn0; m1 = mn1;
            l0 *= corr0; l1 *= corr1;
            #pragma unroll
            for (int nb = 0; nb < 8; nb++) {
                oacc[nb][0] *= corr0; oacc[nb][1] *= corr0;
                oacc[nb][2] *= corr1; oacc[nb][3] *= corr1;
            }

            #pragma unroll
            for (int nb = 0; nb < 4; nb++) {
                sacc[nb][0] = __expf(sacc[nb][0] - mn0);
                sacc[nb][1] = __expf(sacc[nb][1] - mn0);
                sacc[nb][2] = __expf(sacc[nb][2] - mn1);
                sacc[nb][3] = __expf(sacc[nb][3] - mn1);
                l0 += sacc[nb][0] + sacc[nb][1];
                l1 += sacc[nb][2] + sacc[nb][3];
            }

            #pragma unroll
            for (int kc2 = 0; kc2 < 2; kc2++) {
                uint32_t phi[4], plo[4];
                split2(make_float2(sacc[2*kc2][0],     sacc[2*kc2][1]),     phi[0], plo[0]);
                split2(make_float2(sacc[2*kc2][2],     sacc[2*kc2][3]),     phi[1], plo[1]);
                split2(make_float2(sacc[2*kc2 + 1][0], sacc[2*kc2 + 1][1]), phi[2], plo[2]);
                split2(make_float2(sacc[2*kc2 + 1][2], sacc[2*kc2 + 1][3]), phi[3], plo[3]);
                #pragma unroll
                for (int nbp = 0; nbp < 4; nbp++) {
                    uint32_t off = (uint32_t)((nbp * 16 * 20 + kc2 * 8) * 4) + vofsB;
                    uint32_t H[4], L[4];
                    ldm4(H, aVhi + off);
                    ldm4(L, aVlo + off);
                    mma_bf16(oacc[2*nbp],   phi, L[0], L[1]);
                    mma_bf16(oacc[2*nbp],   plo, H[0], H[1]);
                    mma_bf16(oacc[2*nbp],   phi, H[0], H[1]);
                    mma_bf16(oacc[2*nbp+1], phi, L[2], L[3]);
                    mma_bf16(oacc[2*nbp+1], plo, H[2], H[3]);
                    mma_bf16(oacc[2*nbp+1], phi, H[2], H[3]);
                }
            }
        }
        __syncthreads();
    }

    l0 += __shfl_xor_sync(0xffffffffu, l0, 1);
    l0 += __shfl_xor_sync(0xffffffffu, l0, 2);
    l1 += __shfl_xor_sync(0xffffffffu, l1, 1);
    l1 += __shfl_xor_sync(0xffffffffu, l1, 2);
    const float inv0 = 1.f / l0;
    const float inv1 = 1.f / l1;

    float* op0 = O + ((size_t)(b * S_ + r0g)) * 1024 + h * 64;
    float* op1 = O + ((size_t)(b * S_ + r1g)) * 1024 + h * 64;
    #pragma unroll
    for (int nb = 0; nb < 8; nb++) {
        *(float2*)&op0[nb * 8 + 2 * tig] = make_float2(oacc[nb][0] * inv0, oacc[nb][1] * inv0);
        *(float2*)&op1[nb * 8 + 2 * tig] = make_float2(oacc[nb][2] * inv1, oacc[nb][3] * inv1);
    }
}

// ---------------------------------------------------------------------------
// Launch. Inputs: 0 query, 1 key, 2 value, 3 attn_mask, 4 Wq, 5 Wk, 6 Wv, 7 Wo
// ---------------------------------------------------------------------------
extern "C" void kernel_launch(void* const* d_in, const int* in_sizes, int n_in,
                              void* d_out, int out_size)
{
    const float* query = (const float*)d_in[0];
    const float* key   = (const float*)d_in[1];
    const float* value = (const float*)d_in[2];
    const float* Wq    = (const float*)d_in[4];
    const float* Wk    = (const float*)d_in[5];
    const float* Wv    = (const float*)d_in[6];
    const float* Wo    = (const float*)d_in[7];
    float* out = (float*)d_out;

    float* attn;
    cudaGetSymbolAddress((void**)&attn, g_attn);
    __nv_bfloat16 *qah, *qal, *kah, *kal, *vth, *vtl;
    cudaGetSymbolAddress((void**)&qah, g_qah); cudaGetSymbolAddress((void**)&qal, g_qal);
    cudaGetSymbolAddress((void**)&kah, g_kah); cudaGetSymbolAddress((void**)&kal, g_kal);
    cudaGetSymbolAddress((void**)&vth, g_vth); cudaGetSymbolAddress((void**)&vtl, g_vtl);

    const int projsmem = 128 * EPST * 4;        // 67584 B (covers pipeline 61440 too)
    const int gemmsmem = 6 * GSTAGE_F * 4;      // 61440 B
    cudaFuncSetAttribute(proj_kernel,   cudaFuncAttributeMaxDynamicSharedMemorySize, projsmem);
    cudaFuncSetAttribute(gemm_o_kernel, cudaFuncAttributeMaxDynamicSharedMemorySize, gemmsmem);

    // ---- batched projections + fused operand conversion ----
    proj_kernel<<<dim3(8, 32, 3), 256, projsmem>>>(
        query, Wq, key, Wk, value, Wv,
        (uint32_t*)qah, (uint32_t*)qal, (uint32_t*)kah, (uint32_t*)kal,
        (uint32_t*)vth, (uint32_t*)vtl);

    // ---- attention ----
    attn_mma_kernel<<<dim3(S_/ABQ, NH_, B_), 256>>>(
        (const uint32_t*)qah, (const uint32_t*)qal, kah, kal, vth, vtl, attn);

    // ---- output projection ----
    gemm_o_kernel<<<dim3(8, 32), 256, gemmsmem>>>(attn, Wo, out, MTOT, 1024, 1024);
}